// round 9
// baseline (speedup 1.0000x reference)
#include <cuda_runtime.h>
#include <cuda_bf16.h>
#include <math.h>
#include <stdint.h>

// Problem constants
#define BGRAPH 128
#define N0     512
#define EPG    4096
#define FDIM   128
#define NE     (BGRAPH*EPG)     // 524288 edges
#define NT0    (BGRAPH*N0)      // 65536 nodes stage 1
#define OUTSZ  (BGRAPH*256)

// ---------------- device scratch ----------------
__device__ __align__(128) float g_HW[NT0*FDIM];        // x @ W
__device__ __align__(128) float g_H [NT0*FDIM];        // relu(gcn) output
__device__ __align__(128) float g_X [BGRAPH*256*FDIM]; // pooled xnew
__device__ float g_dinv [NT0];
__device__ int   g_esrc[NE];     // compact edge src (global ids), doubles as CSR src
__device__ int   g_edst[NE];     // compact edge dst (global ids)
__device__ int   g_cnt[NT0];
__device__ int   g_off[NT0];
__device__ float g_cnorm[NE];
__device__ int   g_ecnt[BGRAPH];

// ---------------- tf32 helpers ----------------
__device__ __forceinline__ float tf32_hi(float x){
    uint32_t r; asm("cvt.rna.tf32.f32 %0, %1;" : "=r"(r) : "f"(x));
    return __uint_as_float(r);
}
#define MMA_TF32(c, a0,a1,a2,a3, b0,b1) \
    asm volatile("mma.sync.aligned.m16n8k8.row.col.f32.tf32.tf32.f32 " \
        "{%0,%1,%2,%3}, {%4,%5,%6,%7}, {%8,%9}, {%0,%1,%2,%3};" \
        : "+f"((c)[0]), "+f"((c)[1]), "+f"((c)[2]), "+f"((c)[3]) \
        : "r"(a0), "r"(a1), "r"(a2), "r"(a3), "r"(b0), "r"(b1))

#define WPAD 132
#define SM_FLOATS (3*128*WPAD)
#define SM_BYTES  (SM_FLOATS*4)     // 202752

// C[M,128] = A[M,128] @ W[128,128]; 3xTF32 mma.sync; tile = 128 rows/block
__global__ void __launch_bounds__(256, 1) k_gemm_mma(const float* __restrict__ A,
                                                     const float* __restrict__ W){
    extern __shared__ float sm[];
    float* Whi = sm;
    float* Wlo = sm + 128*WPAD;
    float* As  = sm + 2*128*WPAD;
    const int tid  = threadIdx.x;
    const int row0 = blockIdx.x * 128;

    #pragma unroll
    for (int i = 0; i < 16384; i += 256){
        int idx = i + tid;
        int k = idx >> 7, n = idx & 127;
        float v = W[idx];
        float hi = tf32_hi(v);
        Whi[n*WPAD + k] = hi;
        Wlo[n*WPAD + k] = tf32_hi(v - hi);
    }
    {
        const float4* A4 = (const float4*)(A + (size_t)row0 * 128);
        #pragma unroll
        for (int i = 0; i < 16; i++){
            int idx = tid + i*256;
            int r = idx >> 5, c = idx & 31;
            float4 v = A4[idx];
            float* d = As + r*WPAD + c*4;
            d[0]=v.x; d[1]=v.y; d[2]=v.z; d[3]=v.w;
        }
    }
    __syncthreads();

    const int warp = tid >> 5, lane = tid & 31;
    const int g  = lane >> 2;
    const int tg = lane & 3;
    const int ar0 = warp*16 + g;

    float acc[16][4];
    #pragma unroll
    for (int nt = 0; nt < 16; nt++){
        acc[nt][0]=0.f; acc[nt][1]=0.f; acc[nt][2]=0.f; acc[nt][3]=0.f;
    }

    for (int k0 = 0; k0 < 128; k0 += 8){
        float a0 = As[ ar0   *WPAD + k0 + tg    ];
        float a1 = As[(ar0+8)*WPAD + k0 + tg    ];
        float a2 = As[ ar0   *WPAD + k0 + tg + 4];
        float a3 = As[(ar0+8)*WPAD + k0 + tg + 4];
        float h0 = tf32_hi(a0), h1 = tf32_hi(a1), h2 = tf32_hi(a2), h3 = tf32_hi(a3);
        uint32_t ah0 = __float_as_uint(h0), ah1 = __float_as_uint(h1);
        uint32_t ah2 = __float_as_uint(h2), ah3 = __float_as_uint(h3);
        uint32_t al0 = __float_as_uint(tf32_hi(a0 - h0));
        uint32_t al1 = __float_as_uint(tf32_hi(a1 - h1));
        uint32_t al2 = __float_as_uint(tf32_hi(a2 - h2));
        uint32_t al3 = __float_as_uint(tf32_hi(a3 - h3));
        #pragma unroll
        for (int nt = 0; nt < 16; nt++){
            int n = nt*8 + g;
            uint32_t bh0 = __float_as_uint(Whi[n*WPAD + k0 + tg    ]);
            uint32_t bh1 = __float_as_uint(Whi[n*WPAD + k0 + tg + 4]);
            uint32_t bl0 = __float_as_uint(Wlo[n*WPAD + k0 + tg    ]);
            uint32_t bl1 = __float_as_uint(Wlo[n*WPAD + k0 + tg + 4]);
            MMA_TF32(acc[nt], al0,al1,al2,al3, bh0,bh1);
            MMA_TF32(acc[nt], ah0,ah1,ah2,ah3, bl0,bl1);
            MMA_TF32(acc[nt], ah0,ah1,ah2,ah3, bh0,bh1);
        }
    }

    float2* rlo = (float2*)(g_HW + (size_t)(row0 + ar0    ) * 128);
    float2* rhi = (float2*)(g_HW + (size_t)(row0 + ar0 + 8) * 128);
    #pragma unroll
    for (int nt = 0; nt < 16; nt++){
        rlo[nt*4 + tg] = make_float2(acc[nt][0], acc[nt][1]);
        rhi[nt*4 + tg] = make_float2(acc[nt][2], acc[nt][3]);
    }
}

// ---------------- stage-1 CSR build ----------------
__global__ void k_graph(const int* __restrict__ ei){
    __shared__ int   s_cnt[512];
    __shared__ int   s_scan[512];
    __shared__ float s_dinv[512];
    __shared__ int   s_cur[512];
    int g = blockIdx.x, t = threadIdx.x;
    int base = g * EPG;
    s_cnt[t] = 0;
    __syncthreads();

    int ls[8], ld[8];
    #pragma unroll
    for (int i = 0; i < 8; i++){
        int e = base + i*512 + t;
        ls[i] = ei[e]      - g*N0;
        ld[i] = ei[NE + e] - g*N0;
        atomicAdd(&s_cnt[ld[i]], 1);
    }
    __syncthreads();

    int c = s_cnt[t];
    float di = rsqrtf((float)c + 1.f);
    s_dinv[t] = di;
    g_dinv[g*N0 + t] = di;
    g_cnt [g*N0 + t] = c;
    s_scan[t] = c;
    __syncthreads();
    for (int d = 1; d < 512; d <<= 1){
        int add = (t >= d) ? s_scan[t-d] : 0;
        __syncthreads();
        s_scan[t] += add;
        __syncthreads();
    }
    int ex = t ? s_scan[t-1] : 0;
    g_off[g*N0 + t] = base + ex;
    s_cur[t] = ex;
    __syncthreads();

    #pragma unroll
    for (int i = 0; i < 8; i++){
        int p = atomicAdd(&s_cur[ld[i]], 1);
        g_esrc [base + p] = g*N0 + ls[i];
        g_cnorm[base + p] = s_dinv[ls[i]] * s_dinv[ld[i]];
    }
}

// MEGA: block per graph — gather + score + hybrid bitonic topk + pool + readout
// + next-stage graph build
__global__ void __launch_bounds__(512) k_mega(int np, int k,
                                              const float* __restrict__ b,
                                              const float* __restrict__ Ws,
                                              const float* __restrict__ bs,
                                              float* __restrict__ out, int first,
                                              int do_graph, int stage1,
                                              const int* __restrict__ ei){
    __shared__ float s_hs[512];
    __shared__ float skey[512];
    __shared__ int   sidx[512];
    __shared__ int   s_new[512];
    __shared__ float st[256];
    __shared__ int   sold[256];
    __shared__ float s_mx[512];
    __shared__ float s_sm[512];
    __shared__ int   s_cnt2[256];
    __shared__ int   s_scan2[512];
    __shared__ int   s_cur2[256];
    __shared__ float s_dv2[256];
    int g = blockIdx.x, t = threadIdx.x;
    int wid = t >> 5, lane = t & 31;
    int base = g * EPG;

    // ---- gather (16 warps, warp handles np/16 nodes): h = relu(GCN), hs = h.Ws ----
    {
        const float4* HW4 = (const float4*)g_HW;
        float4 bb = ((const float4*)b)[lane];
        float4 wv = ((const float4*)Ws)[lane];
        for (int il = wid; il < np; il += 16){
            int i = g * np + il;
            float di = g_dinv[i];
            float d2 = di * di;
            float4 v = HW4[(size_t)i * 32 + lane];
            float4 acc;
            acc.x = d2 * v.x; acc.y = d2 * v.y; acc.z = d2 * v.z; acc.w = d2 * v.w;
            int off = g_off[i], len = g_cnt[i];
            int e = 0;
            for (; e + 4 <= len; e += 4){
                float n0 = g_cnorm[off+e],   n1 = g_cnorm[off+e+1];
                float n2 = g_cnorm[off+e+2], n3 = g_cnorm[off+e+3];
                int   s0 = g_esrc [off+e],   s1 = g_esrc [off+e+1];
                int   s2 = g_esrc [off+e+2], s3 = g_esrc [off+e+3];
                float4 u0 = HW4[(size_t)s0 * 32 + lane];
                float4 u1 = HW4[(size_t)s1 * 32 + lane];
                float4 u2 = HW4[(size_t)s2 * 32 + lane];
                float4 u3 = HW4[(size_t)s3 * 32 + lane];
                acc.x += n0*u0.x + n1*u1.x + n2*u2.x + n3*u3.x;
                acc.y += n0*u0.y + n1*u1.y + n2*u2.y + n3*u3.y;
                acc.z += n0*u0.z + n1*u1.z + n2*u2.z + n3*u3.z;
                acc.w += n0*u0.w + n1*u1.w + n2*u2.w + n3*u3.w;
            }
            for (; e < len; e++){
                float nr = g_cnorm[off + e];
                int   s  = g_esrc [off + e];
                float4 u = HW4[(size_t)s * 32 + lane];
                acc.x += nr*u.x; acc.y += nr*u.y; acc.z += nr*u.z; acc.w += nr*u.w;
            }
            acc.x = fmaxf(acc.x + bb.x, 0.f);
            acc.y = fmaxf(acc.y + bb.y, 0.f);
            acc.z = fmaxf(acc.z + bb.z, 0.f);
            acc.w = fmaxf(acc.w + bb.w, 0.f);
            ((float4*)g_H)[(size_t)i * 32 + lane] = acc;
            float p = acc.x*wv.x + acc.y*wv.y + acc.z*wv.z + acc.w*wv.w;
            #pragma unroll
            for (int o = 16; o; o >>= 1) p += __shfl_xor_sync(0xffffffffu, p, o);
            if (lane == 0) s_hs[il] = p;
        }
    }
    __syncthreads();

    // ---- score (unrolled x4, hs from smem) ----
    float key; int idx;
    if (t < np){
        int i = g * np + t;
        float di = g_dinv[i];
        float s = di * di * s_hs[t] + bs[0];
        int off = g_off[i], len = g_cnt[i];
        int gnp = g * np;
        int e = 0;
        for (; e + 4 <= len; e += 4){
            int   c0 = g_esrc [off+e]   - gnp, c1 = g_esrc [off+e+1] - gnp;
            int   c2 = g_esrc [off+e+2] - gnp, c3 = g_esrc [off+e+3] - gnp;
            float n0 = g_cnorm[off+e],   n1 = g_cnorm[off+e+1];
            float n2 = g_cnorm[off+e+2], n3 = g_cnorm[off+e+3];
            s += n0*s_hs[c0] + n1*s_hs[c1] + n2*s_hs[c2] + n3*s_hs[c3];
        }
        for (; e < len; e++)
            s += g_cnorm[off + e] * s_hs[g_esrc[off + e] - gnp];
        key = s; idx = t;
    } else {
        key = -INFINITY; idx = 512 + t;   // distinct, sorts last
    }
    s_new[t] = -1;

    // ---- hybrid bitonic sort (desc key, asc idx), elements in registers ----
    for (int size = 2; size <= np; size <<= 1){
        for (int stride = size >> 1; stride > 0; stride >>= 1){
            bool wantDesc = ((t & size) == 0);
            float kp; int ip;
            if (stride >= 32){
                __syncthreads();
                skey[t] = key; sidx[t] = idx;
                __syncthreads();
                int p = t ^ stride;
                kp = skey[p]; ip = sidx[p];
            } else {
                kp = __shfl_xor_sync(0xffffffffu, key, stride);
                ip = __shfl_xor_sync(0xffffffffu, idx, stride);
            }
            int p = t ^ stride;
            bool mine_before = (key > kp) || (key == kp && idx < ip);
            bool keep_mine = ((mine_before == wantDesc) == (t < p));
            if (!keep_mine){ key = kp; idx = ip; }
        }
    }
    __syncthreads();

    if (t < k){
        st[t] = tanhf(key);
        sold[t] = g * np + idx;
        s_new[idx] = t;
    }
    __syncthreads();

    // ---- readout: 4 groups x 128 cols, unrolled x4 ----
    {
        int q = t >> 7, c = t & 127;
        int kq = k >> 2;
        int r0 = q * kq, r1 = r0 + kq;
        float mx = -INFINITY, sum = 0.f;
        for (int r = r0; r < r1; r += 4){
            float v0 = g_H[(size_t)sold[r]  *128 + c] * st[r];
            float v1 = g_H[(size_t)sold[r+1]*128 + c] * st[r+1];
            float v2 = g_H[(size_t)sold[r+2]*128 + c] * st[r+2];
            float v3 = g_H[(size_t)sold[r+3]*128 + c] * st[r+3];
            float* xr = g_X + (size_t)(g * k + r) * 128 + c;
            xr[0] = v0; xr[128] = v1; xr[256] = v2; xr[384] = v3;
            mx = fmaxf(mx, fmaxf(fmaxf(v0, v1), fmaxf(v2, v3)));
            sum += v0 + v1 + v2 + v3;
        }
        s_mx[t] = mx;
        s_sm[t] = sum;
    }
    __syncthreads();
    if (t < 128){
        float m  = fmaxf(fmaxf(s_mx[t], s_mx[t+128]), fmaxf(s_mx[t+256], s_mx[t+384]));
        float sm = s_sm[t] + s_sm[t+128] + s_sm[t+256] + s_sm[t+384];
        if (first){
            out[g*256 + t]       = m;
            out[g*256 + 128 + t] = sm / (float)k;
        } else {
            out[g*256 + t]       += m;
            out[g*256 + 128 + t] += sm / (float)k;
        }
    }

    if (!do_graph) return;

    // ---- next-stage graph build: remap + degree + scan + CSR fill ----
    int ecnt = stage1 ? EPG : g_ecnt[g];
    int na[8], nb[8];
    #pragma unroll
    for (int i = 0; i < 8; i++){
        int e = i*512 + t;
        na[i] = -1; nb[i] = -1;
        if (e < ecnt){
            int a, bn;
            if (stage1){ a = ei[base+e] - g*np;     bn = ei[NE+base+e] - g*np; }
            else       { a = g_esrc[base+e] - g*np; bn = g_edst[base+e] - g*np; }
            na[i] = s_new[a];
            nb[i] = s_new[bn];
        }
    }
    if (t < k) s_cnt2[t] = 0;
    __syncthreads();
    #pragma unroll
    for (int i = 0; i < 8; i++)
        if (na[i] >= 0 && nb[i] >= 0) atomicAdd(&s_cnt2[nb[i]], 1);
    __syncthreads();
    int c2 = 0;
    if (t < k){
        c2 = s_cnt2[t];
        float dv = rsqrtf((float)c2 + 1.f);
        s_dv2[t] = dv;
        g_dinv[g*k + t] = dv;
        g_cnt [g*k + t] = c2;
    }
    s_scan2[t] = (t < k) ? c2 : 0;
    __syncthreads();
    for (int d = 1; d < k; d <<= 1){
        int add = (t >= d) ? s_scan2[t-d] : 0;
        __syncthreads();
        s_scan2[t] += add;
        __syncthreads();
    }
    if (t < k){
        int ex = t ? s_scan2[t-1] : 0;
        g_off[g*k + t] = base + ex;
        s_cur2[t] = ex;
    }
    if (t == k-1) g_ecnt[g] = s_scan2[t];
    __syncthreads();
    #pragma unroll
    for (int i = 0; i < 8; i++){
        if (na[i] >= 0 && nb[i] >= 0){
            int p = atomicAdd(&s_cur2[nb[i]], 1);
            g_esrc [base + p] = g*k + na[i];
            g_edst [base + p] = g*k + nb[i];
            g_cnorm[base + p] = s_dv2[na[i]] * s_dv2[nb[i]];
        }
    }
}

// ---------------- host ----------------
extern "C" void kernel_launch(void* const* d_in, const int* in_sizes, int n_in,
                              void* d_out, int out_size){
    const float* x  = (const float*)d_in[0];
    const int*   ei = (const int*)d_in[1];
    const float* Wm[3]  = {(const float*)d_in[3],  (const float*)d_in[7],  (const float*)d_in[11]};
    const float* bm[3]  = {(const float*)d_in[4],  (const float*)d_in[8],  (const float*)d_in[12]};
    const float* Wsm[3] = {(const float*)d_in[5],  (const float*)d_in[9],  (const float*)d_in[13]};
    const float* bsm[3] = {(const float*)d_in[6],  (const float*)d_in[10], (const float*)d_in[14]};
    float* out = (float*)d_out;

    static cudaStream_t s2 = nullptr;
    static cudaEvent_t ev0 = nullptr, ev1 = nullptr;
    if (!s2){
        cudaStreamCreate(&s2);
        cudaEventCreateWithFlags(&ev0, cudaEventDisableTiming);
        cudaEventCreateWithFlags(&ev1, cudaEventDisableTiming);
        cudaFuncSetAttribute(k_gemm_mma, cudaFuncAttributeMaxDynamicSharedMemorySize, SM_BYTES);
    }

    float* pX = nullptr;
    cudaGetSymbolAddress((void**)&pX, g_X);

    // stage 1: CSR build (side stream) || GEMM (main stream)
    cudaEventRecord(ev0, 0);
    cudaStreamWaitEvent(s2, ev0, 0);
    k_graph<<<BGRAPH, 512, 0, s2>>>(ei);
    cudaEventRecord(ev1, s2);
    k_gemm_mma<<<NT0/128, 256, SM_BYTES>>>(x, Wm[0]);
    cudaStreamWaitEvent(0, ev1, 0);

    k_mega<<<BGRAPH, 512>>>(512, 256, bm[0], Wsm[0], bsm[0], out, 1, 1, 1, ei);

    k_gemm_mma<<<(BGRAPH*256)/128, 256, SM_BYTES>>>(pX, Wm[1]);
    k_mega<<<BGRAPH, 512>>>(256, 128, bm[1], Wsm[1], bsm[1], out, 0, 1, 0, ei);

    k_gemm_mma<<<(BGRAPH*128)/128, 256, SM_BYTES>>>(pX, Wm[2]);
    k_mega<<<BGRAPH, 512>>>(128, 64, bm[2], Wsm[2], bsm[2], out, 0, 0, 0, ei);
}